// round 11
// baseline (speedup 1.0000x reference)
#include <cuda_runtime.h>
#include <cuda_fp16.h>
#include <cstdint>
#include <math.h>

#define BATCH 32
#define LQ    1024
#define LK    1024
#define HID   1024
#define KDIM  1024

// ---------------------------------------------------------------------------
// Device scratch: fp16 hi/lo splits (BSS, no runtime allocation).
// ---------------------------------------------------------------------------
#define QN ((size_t)BATCH * LQ * KDIM)   // 33,554,432
#define WN ((size_t)HID * KDIM)          // 1,048,576
__device__ __half g_qh[QN],  g_ql[QN];
__device__ __half g_kh[QN],  g_kl[QN];
__device__ __half g_wqh[WN], g_wql[WN];
__device__ __half g_wkh[WN], g_wkl[WN];
__device__ __half g_qph[QN], g_qpl[QN];
__device__ __half g_kph[QN], g_kpl[QN];

// ---------------------------------------------------------------------------
// PTX helpers (portable compute_103 ISA: cp.async / ldmatrix / mma.sync)
// ---------------------------------------------------------------------------
__device__ __forceinline__ uint32_t smem_u32(const void* p) {
    uint32_t a;
    asm("{ .reg .u64 t; cvta.to.shared.u64 t, %1; cvt.u32.u64 %0, t; }"
        : "=r"(a) : "l"(p));
    return a;
}

#define CP16(smem, gmem) \
    asm volatile("cp.async.cg.shared.global [%0], [%1], 16;" \
                 :: "r"(smem), "l"(gmem))
#define CP_COMMIT() asm volatile("cp.async.commit_group;" ::: "memory")
#define CP_WAIT1()  asm volatile("cp.async.wait_group 1;" ::: "memory")

#define LDSM4(r, addr) \
    asm volatile("ldmatrix.sync.aligned.m8n8.x4.shared.b16 {%0,%1,%2,%3}, [%4];" \
        : "=r"((r)[0]), "=r"((r)[1]), "=r"((r)[2]), "=r"((r)[3]) : "r"(addr))

// fp32-accumulate HMMA (main hh phase)
#define MMA16816(d, a, b0, b1) \
    asm volatile("mma.sync.aligned.m16n8k16.row.col.f32.f16.f16.f32 " \
        "{%0,%1,%2,%3}, {%4,%5,%6,%7}, {%8,%9}, {%0,%1,%2,%3};" \
        : "+f"((d)[0]), "+f"((d)[1]), "+f"((d)[2]), "+f"((d)[3]) \
        : "r"((a)[0]), "r"((a)[1]), "r"((a)[2]), "r"((a)[3]), \
          "r"(b0), "r"(b1))

// fp16-accumulate HMMA (cross phases; D/C = 2 b32 regs holding 4 halves)
#define MMA16816F16(d, a, b0, b1) \
    asm volatile("mma.sync.aligned.m16n8k16.row.col.f16.f16.f16.f16 " \
        "{%0,%1}, {%2,%3,%4,%5}, {%6,%7}, {%0,%1};" \
        : "+r"((d)[0]), "+r"((d)[1]) \
        : "r"((a)[0]), "r"((a)[1]), "r"((a)[2]), "r"((a)[3]), \
          "r"(b0), "r"(b1))

// ---------------------------------------------------------------------------
// Split fp32 -> (hi, lo) fp16. grid.y selects among up to 2 tensors.
// ---------------------------------------------------------------------------
__global__ void __launch_bounds__(256) split_kernel(
    const float* __restrict__ x0, __half* __restrict__ h0o, __half* __restrict__ l0o,
    const float* __restrict__ x1, __half* __restrict__ h1o, __half* __restrict__ l1o,
    int n4)
{
    const float* x = (blockIdx.y == 0) ? x0 : x1;
    __half* h = (blockIdx.y == 0) ? h0o : h1o;
    __half* l = (blockIdx.y == 0) ? l0o : l1o;
    int i = blockIdx.x * 256 + threadIdx.x;
    if (i >= n4) return;
    float4 v = ((const float4*)x)[i];
    __half h0 = __float2half(v.x);
    __half h1 = __float2half(v.y);
    __half h2 = __float2half(v.z);
    __half h3 = __float2half(v.w);
    __half l0 = __float2half(v.x - __half2float(h0));
    __half l1 = __float2half(v.y - __half2float(h1));
    __half l2 = __float2half(v.z - __half2float(h2));
    __half l3 = __float2half(v.w - __half2float(h3));
    __half2* hp = (__half2*)(h + (size_t)i * 4);
    __half2* lp = (__half2*)(l + (size_t)i * 4);
    hp[0] = __halves2half2(h0, h1);
    hp[1] = __halves2half2(h2, h3);
    lp[0] = __halves2half2(l0, l1);
    lp[1] = __halves2half2(l2, l3);
}

// ---------------------------------------------------------------------------
// fp16x3 NT GEMM on mma.sync: C[M,N] = A[M,K] @ B[N,K]^T, A/B split hi/lo.
// 128x128 CTA tile, K64 STAGES (halved stage count vs K32 to amortize the
// ~1000cyc/stage fixed overhead). 512 threads = 16 warps (4x4), warp 32x32.
// 3-stage cp.async ring (wait_group 1, prefetch t+2).
// SMEM rows 128B data + 16B pad (144B stride; row-start bank = 4r mod 32 ->
// 8 consecutive rows hit distinct banks -> ldmatrix conflict-free).
// Phase hh -> fp32 acc; phases hl+lh -> shared fp16 acc.
// EPI=0: fp32 -> Cf (batched). EPI=1: relu(acc+bias) re-split -> Ch/Cl fp16.
// ---------------------------------------------------------------------------
#define ROWB   144u                      // padded row stride (bytes)
#define ARR_B  (128u * ROWB)             // 18432 per array
#define STG_BYTES (4u * ARR_B)           // 73728 per stage
#define SMEM_BYTES (3u * STG_BYTES)      // 221184

template <int EPI>
__global__ void __launch_bounds__(512, 1) gemm_fp16x3_kernel(
    const __half* __restrict__ Ah, const __half* __restrict__ Al,
    const __half* __restrict__ Bh, const __half* __restrict__ Bl,
    const float* __restrict__ bias,
    float* __restrict__ Cf,
    __half* __restrict__ Ch, __half* __restrict__ Cl,
    int K, long sAz, long sBz, long sCz, int N)
{
    extern __shared__ char smraw[];
    const uint32_t sb = smem_u32(smraw);
    const int tid = threadIdx.x;
    const int wid = tid >> 5;
    const int l   = tid & 31;

    const int bz = blockIdx.z;
    Ah += (long)bz * sAz;  Al += (long)bz * sAz;
    Bh += (long)bz * sBz;  Bl += (long)bz * sBz;
    if (EPI == 0) Cf += (long)bz * sCz;

    const long m0 = (long)blockIdx.y * 128;
    const long n0 = (long)blockIdx.x * 128;

    // --- cp.async coords: 512 threads -> 128 rows x 8 chunks (K64 = 128B) ---
    // 4 threads/row; each thread loads 2 consecutive 16B chunks per array.
    const int lr = tid >> 2;
    const int c0 = (tid & 3) * 2;                 // chunk pair start 0,2,4,6
    const uint32_t srow = (uint32_t)(lr * ROWB + c0 * 16);
    const __half* gAh = Ah + (m0 + lr) * (long)K + c0 * 8;
    const __half* gAl = Al + (m0 + lr) * (long)K + c0 * 8;
    const __half* gBh = Bh + (n0 + lr) * (long)K + c0 * 8;
    const __half* gBl = Bl + (n0 + lr) * (long)K + c0 * 8;

    // --- ldmatrix per-lane offsets (4x4 warp grid, warp tile 32x32) ---
    const int warpM = (wid >> 2) * 32;
    const int warpN = (wid & 3) * 32;
    const uint32_t aoff = (uint32_t)((warpM + (l & 15)) * ROWB + (l >> 4) * 16);
    const uint32_t boff = (uint32_t)((warpN + (l & 7) + ((l >> 4) << 3)) * ROWB +
                                     (((l >> 3) & 1) ? 16 : 0));

    auto load_stage = [&](int stage, int k0) {
        const uint32_t s = sb + (uint32_t)stage * STG_BYTES + srow;
        CP16(s,                  gAh + k0);
        CP16(s + 16,             gAh + k0 + 8);
        CP16(s + ARR_B,          gAl + k0);
        CP16(s + ARR_B + 16,     gAl + k0 + 8);
        CP16(s + 2 * ARR_B,      gBh + k0);
        CP16(s + 2 * ARR_B + 16, gBh + k0 + 8);
        CP16(s + 3 * ARR_B,      gBl + k0);
        CP16(s + 3 * ARR_B + 16, gBl + k0 + 8);
    };

    float acc[2][4][4];
    uint32_t accx[2][4][2];          // fp16x2 cross-term accumulators
#pragma unroll
    for (int i = 0; i < 2; i++)
#pragma unroll
        for (int j = 0; j < 4; j++) {
#pragma unroll
            for (int r = 0; r < 4; r++) acc[i][j][r] = 0.0f;
            accx[i][j][0] = 0u;
            accx[i][j][1] = 0u;
        }

    const int NK = K >> 6;   // K64 stages (16 for K=1024)

    load_stage(0, 0);  CP_COMMIT();
    load_stage(1, 64); CP_COMMIT();

    for (int t = 0; t < NK; t++) {
        CP_WAIT1();          // stage t complete (1 newer group may be in flight)
        __syncthreads();

        const int tn2 = t + 2;
        if (tn2 < NK) load_stage(tn2 % 3, tn2 * 64);
        CP_COMMIT();         // uniform group numbering

        const uint32_t sbase = sb + (uint32_t)(t % 3) * STG_BYTES;
#pragma unroll
        for (int ks = 0; ks < 4; ks++) {
            uint32_t ah[2][4], al[2][4], bh[2][4], bl[2][4];
            // Burst 1: hi fragments
#pragma unroll
            for (int mt = 0; mt < 2; mt++)
                LDSM4(ah[mt], sbase + aoff + mt * (16 * ROWB) + ks * 32);
#pragma unroll
            for (int np = 0; np < 2; np++)
                LDSM4(bh[np], sbase + 2 * ARR_B + boff + np * (16 * ROWB) + ks * 32);
            // Phase hh (fp32 acc)
#pragma unroll
            for (int mt = 0; mt < 2; mt++)
#pragma unroll
                for (int nt = 0; nt < 4; nt++)
                    MMA16816(acc[mt][nt], ah[mt],
                             bh[nt >> 1][(nt & 1) * 2], bh[nt >> 1][(nt & 1) * 2 + 1]);
            // Burst 2: lo fragments (hidden behind hh MMAs)
#pragma unroll
            for (int mt = 0; mt < 2; mt++)
                LDSM4(al[mt], sbase + ARR_B + aoff + mt * (16 * ROWB) + ks * 32);
#pragma unroll
            for (int np = 0; np < 2; np++)
                LDSM4(bl[np], sbase + 3 * ARR_B + boff + np * (16 * ROWB) + ks * 32);
            // Phase hl (fp16 acc)
#pragma unroll
            for (int mt = 0; mt < 2; mt++)
#pragma unroll
                for (int nt = 0; nt < 4; nt++)
                    MMA16816F16(accx[mt][nt], ah[mt],
                                bl[nt >> 1][(nt & 1) * 2], bl[nt >> 1][(nt & 1) * 2 + 1]);
            // Phase lh (fp16 acc, same accumulator)
#pragma unroll
            for (int mt = 0; mt < 2; mt++)
#pragma unroll
                for (int nt = 0; nt < 4; nt++)
                    MMA16816F16(accx[mt][nt], al[mt],
                                bh[nt >> 1][(nt & 1) * 2], bh[nt >> 1][(nt & 1) * 2 + 1]);
        }
    }

    // --- Epilogue: total = acc(fp32 hh) + accx(fp16 hl+lh) ---
    const int tm = l >> 2;          // 0..7
    const int tn = (l & 3) * 2;     // 0,2,4,6
#pragma unroll
    for (int mt = 0; mt < 2; mt++) {
        const long r0 = m0 + warpM + mt * 16 + tm;
        const long r1 = r0 + 8;
#pragma unroll
        for (int nt = 0; nt < 4; nt++) {
            const long col = n0 + warpN + nt * 8 + tn;
            float2 x01 = __half22float2(*(__half2*)&accx[mt][nt][0]);
            float2 x23 = __half22float2(*(__half2*)&accx[mt][nt][1]);
            float c0 = acc[mt][nt][0] + x01.x;
            float c1 = acc[mt][nt][1] + x01.y;
            float c2 = acc[mt][nt][2] + x23.x;
            float c3 = acc[mt][nt][3] + x23.y;
            if (EPI == 0) {
                *(float2*)(Cf + r0 * (long)N + col) = make_float2(c0, c1);
                *(float2*)(Cf + r1 * (long)N + col) = make_float2(c2, c3);
            } else {
                const float b0 = bias[col], b1 = bias[col + 1];
                float v0 = fmaxf(c0 + b0, 0.0f);
                float v1 = fmaxf(c1 + b1, 0.0f);
                float v2 = fmaxf(c2 + b0, 0.0f);
                float v3 = fmaxf(c3 + b1, 0.0f);
                __half h0 = __float2half(v0), h1 = __float2half(v1);
                __half h2 = __float2half(v2), h3 = __float2half(v3);
                __half e0 = __float2half(v0 - __half2float(h0));
                __half e1 = __float2half(v1 - __half2float(h1));
                __half e2 = __float2half(v2 - __half2float(h2));
                __half e3 = __float2half(v3 - __half2float(h3));
                *(__half2*)(Ch + r0 * (long)N + col) = __halves2half2(h0, h1);
                *(__half2*)(Ch + r1 * (long)N + col) = __halves2half2(h2, h3);
                *(__half2*)(Cl + r0 * (long)N + col) = __halves2half2(e0, e1);
                *(__half2*)(Cl + r1 * (long)N + col) = __halves2half2(e2, e3);
            }
        }
    }
}

// ---------------------------------------------------------------------------
// Masked softmax (near roofline; unchanged)
// ---------------------------------------------------------------------------
__global__ void __launch_bounds__(256) masked_softmax_kernel(
    float* __restrict__ logits,
    const int* __restrict__ key_mask,
    const int* __restrict__ query_mask)
{
    const long row = blockIdx.x;
    const int  b   = (int)(row >> 10);
    float* ptr = logits + (row << 10);
    const int4* km4 = (const int4*)(key_mask + ((long)b << 10));
    const int tid = threadIdx.x;

    float4 v = ((const float4*)ptr)[tid];
    int4   m = km4[tid];
    float x0 = m.x ? v.x : -1e9f;
    float x1 = m.y ? v.y : -1e9f;
    float x2 = m.z ? v.z : -1e9f;
    float x3 = m.w ? v.w : -1e9f;

    __shared__ float smx[8];
    __shared__ float ssum[8];

    float mx = fmaxf(fmaxf(x0, x1), fmaxf(x2, x3));
#pragma unroll
    for (int o = 16; o > 0; o >>= 1)
        mx = fmaxf(mx, __shfl_xor_sync(0xFFFFFFFFu, mx, o));
    if ((tid & 31) == 0) smx[tid >> 5] = mx;
    __syncthreads();
    float bmx = smx[0];
#pragma unroll
    for (int w = 1; w < 8; w++) bmx = fmaxf(bmx, smx[w]);

    float e0 = expf(x0 - bmx);
    float e1 = expf(x1 - bmx);
    float e2 = expf(x2 - bmx);
    float e3 = expf(x3 - bmx);
    float s = e0 + e1 + e2 + e3;
#pragma unroll
    for (int o = 16; o > 0; o >>= 1)
        s += __shfl_xor_sync(0xFFFFFFFFu, s, o);
    if ((tid & 31) == 0) ssum[tid >> 5] = s;
    __syncthreads();
    float bs = 0.0f;
#pragma unroll
    for (int w = 0; w < 8; w++) bs += ssum[w];

    const float qmf = (float)query_mask[row];
    const float inv = qmf / bs;
    v.x = e0 * inv;
    v.y = e1 * inv;
    v.z = e2 * inv;
    v.w = e3 * inv;
    ((float4*)ptr)[tid] = v;
}

// ---------------------------------------------------------------------------
// kernel_launch
// Inputs: query, key, query_mask, key_mask, Wq, bq, Wk, bk
// ---------------------------------------------------------------------------
extern "C" void kernel_launch(void* const* d_in, const int* in_sizes, int n_in,
                              void* d_out, int out_size)
{
    const float* query = (const float*)d_in[0];
    const float* key   = (const float*)d_in[1];
    const int*   qmask = (const int*)  d_in[2];
    const int*   kmask = (const int*)  d_in[3];
    const float* Wq    = (const float*)d_in[4];
    const float* bq    = (const float*)d_in[5];
    const float* Wk    = (const float*)d_in[6];
    const float* bk    = (const float*)d_in[7];
    float* out = (float*)d_out;

    __half *qh, *ql, *kh, *kl, *wqh, *wql, *wkh, *wkl;
    __half *qph, *qpl, *kph, *kpl;
    cudaGetSymbolAddress((void**)&qh,  g_qh);
    cudaGetSymbolAddress((void**)&ql,  g_ql);
    cudaGetSymbolAddress((void**)&kh,  g_kh);
    cudaGetSymbolAddress((void**)&kl,  g_kl);
    cudaGetSymbolAddress((void**)&wqh, g_wqh);
    cudaGetSymbolAddress((void**)&wql, g_wql);
    cudaGetSymbolAddress((void**)&wkh, g_wkh);
    cudaGetSymbolAddress((void**)&wkl, g_wkl);
    cudaGetSymbolAddress((void**)&qph, g_qph);
    cudaGetSymbolAddress((void**)&qpl, g_qpl);
    cudaGetSymbolAddress((void**)&kph, g_kph);
    cudaGetSymbolAddress((void**)&kpl, g_kpl);

    cudaFuncSetAttribute(gemm_fp16x3_kernel<0>,
                         cudaFuncAttributeMaxDynamicSharedMemorySize, SMEM_BYTES);
    cudaFuncSetAttribute(gemm_fp16x3_kernel<1>,
                         cudaFuncAttributeMaxDynamicSharedMemorySize, SMEM_BYTES);

    // Split fp32 inputs into fp16 hi/lo (query+key fused; Wq+Wk fused)
    dim3 gs_big((unsigned)((QN / 4) / 256), 2);   // 32768 x 2
    split_kernel<<<gs_big, 256>>>(query, qh, ql, key, kh, kl, (int)(QN / 4));
    dim3 gs_w((unsigned)((WN / 4) / 256), 2);     // 1024 x 2
    split_kernel<<<gs_w, 256>>>(Wq, wqh, wql, Wk, wkh, wkl, (int)(WN / 4));

    // Projections: relu(X @ W^T + b), outputs re-split to fp16 hi/lo
    dim3 gproj(HID / 128, (BATCH * LQ) / 128, 1);
    gemm_fp16x3_kernel<1><<<gproj, 512, SMEM_BYTES>>>(
        qh, ql, wqh, wql, bq, nullptr, qph, qpl, KDIM, 0, 0, 0, HID);
    gemm_fp16x3_kernel<1><<<gproj, 512, SMEM_BYTES>>>(
        kh, kl, wkh, wkl, bk, nullptr, kph, kpl, KDIM, 0, 0, 0, HID);

    // Batched logits: q_b @ k_b^T -> d_out (fp32)
    dim3 glog(LK / 128, LQ / 128, BATCH);
    gemm_fp16x3_kernel<0><<<glog, 512, SMEM_BYTES>>>(
        qph, qpl, kph, kpl, nullptr, out, nullptr, nullptr, HID,
        (long)LQ * HID, (long)LK * HID, (long)LQ * LK, LK);

    // Masked softmax + query-mask
    masked_softmax_kernel<<<BATCH * LQ, 256>>>(out, kmask, qmask);
}

// round 12
// speedup vs baseline: 1.0329x; 1.0329x over previous
#include <cuda_runtime.h>
#include <cuda_fp16.h>
#include <cstdint>
#include <math.h>

#define BATCH 32
#define LQ    1024
#define LK    1024
#define HID   1024
#define KDIM  1024

// ---------------------------------------------------------------------------
// Device scratch: fp16 hi/lo splits (BSS, no runtime allocation).
// ---------------------------------------------------------------------------
#define QN ((size_t)BATCH * LQ * KDIM)   // 33,554,432
#define WN ((size_t)HID * KDIM)          // 1,048,576
__device__ __half g_qh[QN],  g_ql[QN];
__device__ __half g_kh[QN],  g_kl[QN];
__device__ __half g_wqh[WN], g_wql[WN];
__device__ __half g_wkh[WN], g_wkl[WN];
__device__ __half g_qph[QN], g_qpl[QN];
__device__ __half g_kph[QN], g_kpl[QN];

// ---------------------------------------------------------------------------
// PTX helpers (portable compute_103 ISA: cp.async / ldmatrix / mma.sync)
// ---------------------------------------------------------------------------
__device__ __forceinline__ uint32_t smem_u32(const void* p) {
    uint32_t a;
    asm("{ .reg .u64 t; cvta.to.shared.u64 t, %1; cvt.u32.u64 %0, t; }"
        : "=r"(a) : "l"(p));
    return a;
}

#define CP16(smem, gmem) \
    asm volatile("cp.async.cg.shared.global [%0], [%1], 16;" \
                 :: "r"(smem), "l"(gmem))
#define CP_COMMIT() asm volatile("cp.async.commit_group;" ::: "memory")
#define CP_WAIT2()  asm volatile("cp.async.wait_group 2;" ::: "memory")

#define LDSM4(r, addr) \
    asm volatile("ldmatrix.sync.aligned.m8n8.x4.shared.b16 {%0,%1,%2,%3}, [%4];" \
        : "=r"((r)[0]), "=r"((r)[1]), "=r"((r)[2]), "=r"((r)[3]) : "r"(addr))

// fp32-accumulate HMMA (main hh phase)
#define MMA16816(d, a, b0, b1) \
    asm volatile("mma.sync.aligned.m16n8k16.row.col.f32.f16.f16.f32 " \
        "{%0,%1,%2,%3}, {%4,%5,%6,%7}, {%8,%9}, {%0,%1,%2,%3};" \
        : "+f"((d)[0]), "+f"((d)[1]), "+f"((d)[2]), "+f"((d)[3]) \
        : "r"((a)[0]), "r"((a)[1]), "r"((a)[2]), "r"((a)[3]), \
          "r"(b0), "r"(b1))

// fp16-accumulate HMMA (cross phases; D/C = 2 b32 regs holding 4 halves)
#define MMA16816F16(d, a, b0, b1) \
    asm volatile("mma.sync.aligned.m16n8k16.row.col.f16.f16.f16.f16 " \
        "{%0,%1}, {%2,%3,%4,%5}, {%6,%7}, {%0,%1};" \
        : "+r"((d)[0]), "+r"((d)[1]) \
        : "r"((a)[0]), "r"((a)[1]), "r"((a)[2]), "r"((a)[3]), \
          "r"(b0), "r"(b1))

// ---------------------------------------------------------------------------
// Split fp32 -> (hi, lo) fp16. grid.y selects among up to 2 tensors.
// ---------------------------------------------------------------------------
__global__ void __launch_bounds__(256) split_kernel(
    const float* __restrict__ x0, __half* __restrict__ h0o, __half* __restrict__ l0o,
    const float* __restrict__ x1, __half* __restrict__ h1o, __half* __restrict__ l1o,
    int n4)
{
    const float* x = (blockIdx.y == 0) ? x0 : x1;
    __half* h = (blockIdx.y == 0) ? h0o : h1o;
    __half* l = (blockIdx.y == 0) ? l0o : l1o;
    int i = blockIdx.x * 256 + threadIdx.x;
    if (i >= n4) return;
    float4 v = ((const float4*)x)[i];
    __half h0 = __float2half(v.x);
    __half h1 = __float2half(v.y);
    __half h2 = __float2half(v.z);
    __half h3 = __float2half(v.w);
    __half l0 = __float2half(v.x - __half2float(h0));
    __half l1 = __float2half(v.y - __half2float(h1));
    __half l2 = __float2half(v.z - __half2float(h2));
    __half l3 = __float2half(v.w - __half2float(h3));
    __half2* hp = (__half2*)(h + (size_t)i * 4);
    __half2* lp = (__half2*)(l + (size_t)i * 4);
    hp[0] = __halves2half2(h0, h1);
    hp[1] = __halves2half2(h2, h3);
    lp[0] = __halves2half2(l0, l1);
    lp[1] = __halves2half2(l2, l3);
}

// ---------------------------------------------------------------------------
// fp16x3 NT GEMM on mma.sync: C[M,N] = A[M,K] @ B[N,K]^T, A/B split hi/lo.
// 128x128x32 CTA tile, 512 threads = 16 warps (4x4), warp tile 32x32.
// 4-stage cp.async ring (wait_group 2, prefetch t+3).
// Loader REPOSITIONED: cp.async for stage t+3 issues after the hh MMA phase
// of ks=0, off the stage-start LSU burst (LDSM + LDGSTS convoy).
// Phase hh -> fp32 acc; phases hl+lh -> shared fp16 acc.
// SMEM rows padded to 80B (20-bank stride -> conflict-free ldmatrix).
// EPI=0: fp32 -> Cf (batched). EPI=1: relu(acc+bias) re-split -> Ch/Cl fp16.
// ---------------------------------------------------------------------------
#define STG_BYTES 40960u           // 4 arrays * 128 rows * 80B
#define SMEM_BYTES (4u * STG_BYTES)

template <int EPI>
__global__ void __launch_bounds__(512, 1) gemm_fp16x3_kernel(
    const __half* __restrict__ Ah, const __half* __restrict__ Al,
    const __half* __restrict__ Bh, const __half* __restrict__ Bl,
    const float* __restrict__ bias,
    float* __restrict__ Cf,
    __half* __restrict__ Ch, __half* __restrict__ Cl,
    int K, long sAz, long sBz, long sCz, int N)
{
    extern __shared__ char smraw[];
    const uint32_t sb = smem_u32(smraw);
    const int tid = threadIdx.x;
    const int wid = tid >> 5;
    const int l   = tid & 31;

    const int bz = blockIdx.z;
    Ah += (long)bz * sAz;  Al += (long)bz * sAz;
    Bh += (long)bz * sBz;  Bl += (long)bz * sBz;
    if (EPI == 0) Cf += (long)bz * sCz;

    const long m0 = (long)blockIdx.y * 128;
    const long n0 = (long)blockIdx.x * 128;

    // --- cp.async coords: 512 threads -> (row 0..127, 16B chunk 0..3) ---
    const int lr = tid >> 2;
    const int lc = tid & 3;
    const uint32_t srow = (uint32_t)(lr * 80 + lc * 16);
    const __half* gAh = Ah + (m0 + lr) * (long)K + lc * 8;
    const __half* gAl = Al + (m0 + lr) * (long)K + lc * 8;
    const __half* gBh = Bh + (n0 + lr) * (long)K + lc * 8;
    const __half* gBl = Bl + (n0 + lr) * (long)K + lc * 8;

    // --- ldmatrix per-lane offsets (4x4 warp grid, warp tile 32x32) ---
    const int warpM = (wid >> 2) * 32;
    const int warpN = (wid & 3) * 32;
    const uint32_t aoff = (uint32_t)((warpM + (l & 15)) * 80 + (l >> 4) * 16);
    const uint32_t boff = (uint32_t)((warpN + (l & 7) + ((l >> 4) << 3)) * 80 +
                                     (((l >> 3) & 1) ? 16 : 0));

    auto load_stage = [&](int stage, int k0) {
        const uint32_t s = sb + (uint32_t)stage * STG_BYTES + srow;
        CP16(s,         gAh + k0);
        CP16(s + 10240, gAl + k0);
        CP16(s + 20480, gBh + k0);
        CP16(s + 30720, gBl + k0);
    };

    float acc[2][4][4];
    uint32_t accx[2][4][2];          // fp16x2 cross-term accumulators
#pragma unroll
    for (int i = 0; i < 2; i++)
#pragma unroll
        for (int j = 0; j < 4; j++) {
#pragma unroll
            for (int r = 0; r < 4; r++) acc[i][j][r] = 0.0f;
            accx[i][j][0] = 0u;
            accx[i][j][1] = 0u;
        }

    const int NK = K >> 5;   // K32 stages

    load_stage(0, 0);  CP_COMMIT();
    load_stage(1, 32); CP_COMMIT();
    load_stage(2, 64); CP_COMMIT();

    for (int t = 0; t < NK; t++) {
        CP_WAIT2();          // group t complete (2 newer groups may be in flight)
        __syncthreads();

        const uint32_t sbase = sb + (uint32_t)(t & 3) * STG_BYTES;
#pragma unroll
        for (int ks = 0; ks < 2; ks++) {
            uint32_t ah[2][4], al[2][4], bh[2][4], bl[2][4];
            // Burst 1: hi fragments
#pragma unroll
            for (int mt = 0; mt < 2; mt++)
                LDSM4(ah[mt], sbase + aoff + mt * 1280 + ks * 32);
#pragma unroll
            for (int np = 0; np < 2; np++)
                LDSM4(bh[np], sbase + 20480 + boff + np * 1280 + ks * 32);
            // Phase hh (fp32 acc)
#pragma unroll
            for (int mt = 0; mt < 2; mt++)
#pragma unroll
                for (int nt = 0; nt < 4; nt++)
                    MMA16816(acc[mt][nt], ah[mt],
                             bh[nt >> 1][(nt & 1) * 2], bh[nt >> 1][(nt & 1) * 2 + 1]);
            // Loader for stage t+3, off the stage-start LSU burst (ks==0 only).
            if (ks == 0) {
                const int tn3 = t + 3;
                if (tn3 < NK) load_stage(tn3 & 3, tn3 * 32);
                CP_COMMIT();     // uniform group numbering (one commit per t)
            }
            // Burst 2: lo fragments (hidden behind hh MMAs)
#pragma unroll
            for (int mt = 0; mt < 2; mt++)
                LDSM4(al[mt], sbase + 10240 + aoff + mt * 1280 + ks * 32);
#pragma unroll
            for (int np = 0; np < 2; np++)
                LDSM4(bl[np], sbase + 30720 + boff + np * 1280 + ks * 32);
            // Phase hl (fp16 acc)
#pragma unroll
            for (int mt = 0; mt < 2; mt++)
#pragma unroll
                for (int nt = 0; nt < 4; nt++)
                    MMA16816F16(accx[mt][nt], ah[mt],
                                bl[nt >> 1][(nt & 1) * 2], bl[nt >> 1][(nt & 1) * 2 + 1]);
            // Phase lh (fp16 acc, same accumulator)
#pragma unroll
            for (int mt = 0; mt < 2; mt++)
#pragma unroll
                for (int nt = 0; nt < 4; nt++)
                    MMA16816F16(accx[mt][nt], al[mt],
                                bh[nt >> 1][(nt & 1) * 2], bh[nt >> 1][(nt & 1) * 2 + 1]);
        }
    }

    // --- Epilogue: total = acc(fp32 hh) + accx(fp16 hl+lh) ---
    const int tm = l >> 2;          // 0..7
    const int tn = (l & 3) * 2;     // 0,2,4,6
#pragma unroll
    for (int mt = 0; mt < 2; mt++) {
        const long r0 = m0 + warpM + mt * 16 + tm;
        const long r1 = r0 + 8;
#pragma unroll
        for (int nt = 0; nt < 4; nt++) {
            const long col = n0 + warpN + nt * 8 + tn;
            float2 x01 = __half22float2(*(__half2*)&accx[mt][nt][0]);
            float2 x23 = __half22float2(*(__half2*)&accx[mt][nt][1]);
            float c0 = acc[mt][nt][0] + x01.x;
            float c1 = acc[mt][nt][1] + x01.y;
            float c2 = acc[mt][nt][2] + x23.x;
            float c3 = acc[mt][nt][3] + x23.y;
            if (EPI == 0) {
                *(float2*)(Cf + r0 * (long)N + col) = make_float2(c0, c1);
                *(float2*)(Cf + r1 * (long)N + col) = make_float2(c2, c3);
            } else {
                const float b0 = bias[col], b1 = bias[col + 1];
                float v0 = fmaxf(c0 + b0, 0.0f);
                float v1 = fmaxf(c1 + b1, 0.0f);
                float v2 = fmaxf(c2 + b0, 0.0f);
                float v3 = fmaxf(c3 + b1, 0.0f);
                __half h0 = __float2half(v0), h1 = __float2half(v1);
                __half h2 = __float2half(v2), h3 = __float2half(v3);
                __half e0 = __float2half(v0 - __half2float(h0));
                __half e1 = __float2half(v1 - __half2float(h1));
                __half e2 = __float2half(v2 - __half2float(h2));
                __half e3 = __float2half(v3 - __half2float(h3));
                *(__half2*)(Ch + r0 * (long)N + col) = __halves2half2(h0, h1);
                *(__half2*)(Ch + r1 * (long)N + col) = __halves2half2(h2, h3);
                *(__half2*)(Cl + r0 * (long)N + col) = __halves2half2(e0, e1);
                *(__half2*)(Cl + r1 * (long)N + col) = __halves2half2(e2, e3);
            }
        }
    }
}

// ---------------------------------------------------------------------------
// Masked softmax (near roofline; unchanged)
// ---------------------------------------------------------------------------
__global__ void __launch_bounds__(256) masked_softmax_kernel(
    float* __restrict__ logits,
    const int* __restrict__ key_mask,
    const int* __restrict__ query_mask)
{
    const long row = blockIdx.x;
    const int  b   = (int)(row >> 10);
    float* ptr = logits + (row << 10);
    const int4* km4 = (const int4*)(key_mask + ((long)b << 10));
    const int tid = threadIdx.x;

    float4 v = ((const float4*)ptr)[tid];
    int4   m = km4[tid];
    float x0 = m.x ? v.x : -1e9f;
    float x1 = m.y ? v.y : -1e9f;
    float x2 = m.z ? v.z : -1e9f;
    float x3 = m.w ? v.w : -1e9f;

    __shared__ float smx[8];
    __shared__ float ssum[8];

    float mx = fmaxf(fmaxf(x0, x1), fmaxf(x2, x3));
#pragma unroll
    for (int o = 16; o > 0; o >>= 1)
        mx = fmaxf(mx, __shfl_xor_sync(0xFFFFFFFFu, mx, o));
    if ((tid & 31) == 0) smx[tid >> 5] = mx;
    __syncthreads();
    float bmx = smx[0];
#pragma unroll
    for (int w = 1; w < 8; w++) bmx = fmaxf(bmx, smx[w]);

    float e0 = expf(x0 - bmx);
    float e1 = expf(x1 - bmx);
    float e2 = expf(x2 - bmx);
    float e3 = expf(x3 - bmx);
    float s = e0 + e1 + e2 + e3;
#pragma unroll
    for (int o = 16; o > 0; o >>= 1)
        s += __shfl_xor_sync(0xFFFFFFFFu, s, o);
    if ((tid & 31) == 0) ssum[tid >> 5] = s;
    __syncthreads();
    float bs = 0.0f;
#pragma unroll
    for (int w = 0; w < 8; w++) bs += ssum[w];

    const float qmf = (float)query_mask[row];
    const float inv = qmf / bs;
    v.x = e0 * inv;
    v.y = e1 * inv;
    v.z = e2 * inv;
    v.w = e3 * inv;
    ((float4*)ptr)[tid] = v;
}

// ---------------------------------------------------------------------------
// kernel_launch
// Inputs: query, key, query_mask, key_mask, Wq, bq, Wk, bk
// ---------------------------------------------------------------------------
extern "C" void kernel_launch(void* const* d_in, const int* in_sizes, int n_in,
                              void* d_out, int out_size)
{
    const float* query = (const float*)d_in[0];
    const float* key   = (const float*)d_in[1];
    const int*   qmask = (const int*)  d_in[2];
    const int*   kmask = (const int*)  d_in[3];
    const float* Wq    = (const float*)d_in[4];
    const float* bq    = (const float*)d_in[5];
    const float* Wk    = (const float*)d_in[6];
    const float* bk    = (const float*)d_in[7];
    float* out = (float*)d_out;

    __half *qh, *ql, *kh, *kl, *wqh, *wql, *wkh, *wkl;
    __half *qph, *qpl, *kph, *kpl;
    cudaGetSymbolAddress((void**)&qh,  g_qh);
    cudaGetSymbolAddress((void**)&ql,  g_ql);
    cudaGetSymbolAddress((void**)&kh,  g_kh);
    cudaGetSymbolAddress((void**)&kl,  g_kl);
    cudaGetSymbolAddress((void**)&wqh, g_wqh);
    cudaGetSymbolAddress((void**)&wql, g_wql);
    cudaGetSymbolAddress((void**)&wkh, g_wkh);
    cudaGetSymbolAddress((void**)&wkl, g_wkl);
    cudaGetSymbolAddress((void**)&qph, g_qph);
    cudaGetSymbolAddress((void**)&qpl, g_qpl);
    cudaGetSymbolAddress((void**)&kph, g_kph);
    cudaGetSymbolAddress((void**)&kpl, g_kpl);

    cudaFuncSetAttribute(gemm_fp16x3_kernel<0>,
                         cudaFuncAttributeMaxDynamicSharedMemorySize, SMEM_BYTES);
    cudaFuncSetAttribute(gemm_fp16x3_kernel<1>,
                         cudaFuncAttributeMaxDynamicSharedMemorySize, SMEM_BYTES);

    // Split fp32 inputs into fp16 hi/lo (query+key fused; Wq+Wk fused)
    dim3 gs_big((unsigned)((QN / 4) / 256), 2);   // 32768 x 2
    split_kernel<<<gs_big, 256>>>(query, qh, ql, key, kh, kl, (int)(QN / 4));
    dim3 gs_w((unsigned)((WN / 4) / 256), 2);     // 1024 x 2
    split_kernel<<<gs_w, 256>>>(Wq, wqh, wql, Wk, wkh, wkl, (int)(WN / 4));

    // Projections: relu(X @ W^T + b), outputs re-split to fp16 hi/lo
    dim3 gproj(HID / 128, (BATCH * LQ) / 128, 1);
    gemm_fp16x3_kernel<1><<<gproj, 512, SMEM_BYTES>>>(
        qh, ql, wqh, wql, bq, nullptr, qph, qpl, KDIM, 0, 0, 0, HID);
    gemm_fp16x3_kernel<1><<<gproj, 512, SMEM_BYTES>>>(
        kh, kl, wkh, wkl, bk, nullptr, kph, kpl, KDIM, 0, 0, 0, HID);

    // Batched logits: q_b @ k_b^T -> d_out (fp32)
    dim3 glog(LK / 128, LQ / 128, BATCH);
    gemm_fp16x3_kernel<0><<<glog, 512, SMEM_BYTES>>>(
        qph, qpl, kph, kpl, nullptr, out, nullptr, nullptr, HID,
        (long)LQ * HID, (long)LK * HID, (long)LQ * LK, LK);

    // Masked softmax + query-mask
    masked_softmax_kernel<<<BATCH * LQ, 256>>>(out, kmask, qmask);
}

// round 13
// speedup vs baseline: 1.8973x; 1.8369x over previous
#include <cuda_runtime.h>
#include <cuda_fp16.h>
#include <cstdint>
#include <math.h>

#define BATCH 32
#define LQ    1024
#define LK    1024
#define HID   1024
#define KDIM  1024

// ---------------------------------------------------------------------------
// Device scratch (BSS, no runtime allocation).
// ---------------------------------------------------------------------------
#define QN ((size_t)BATCH * LQ * KDIM)   // 33,554,432
#define WN ((size_t)HID * KDIM)          // 1,048,576
__device__ __half g_qh[QN],  g_ql[QN];
__device__ __half g_kh[QN],  g_kl[QN];
__device__ __half g_wqh[WN], g_wql[WN];
__device__ __half g_wkh[WN], g_wkl[WN];
__device__ __half g_qph[QN], g_qpl[QN];   // compacted projected q (hi/lo)
__device__ __half g_kph[QN], g_kpl[QN];   // compacted projected k (hi/lo)
__device__ float  g_logc[QN];             // compacted logits (128 MB)
__device__ int    g_qidx[BATCH * LQ];     // per-batch permutation: selected, then complement
__device__ int    g_kidx[BATCH * LK];
__device__ int    g_qcnt[BATCH];
__device__ int    g_kcnt[BATCH];

// ---------------------------------------------------------------------------
// PTX helpers (portable compute_103 ISA: cp.async / ldmatrix / mma.sync)
// ---------------------------------------------------------------------------
__device__ __forceinline__ uint32_t smem_u32(const void* p) {
    uint32_t a;
    asm("{ .reg .u64 t; cvta.to.shared.u64 t, %1; cvt.u32.u64 %0, t; }"
        : "=r"(a) : "l"(p));
    return a;
}

#define CP16(smem, gmem) \
    asm volatile("cp.async.cg.shared.global [%0], [%1], 16;" \
                 :: "r"(smem), "l"(gmem))
#define CP_COMMIT() asm volatile("cp.async.commit_group;" ::: "memory")
#define CP_WAIT2()  asm volatile("cp.async.wait_group 2;" ::: "memory")

#define LDSM4(r, addr) \
    asm volatile("ldmatrix.sync.aligned.m8n8.x4.shared.b16 {%0,%1,%2,%3}, [%4];" \
        : "=r"((r)[0]), "=r"((r)[1]), "=r"((r)[2]), "=r"((r)[3]) : "r"(addr))

// fp32-accumulate HMMA (main hh phase)
#define MMA16816(d, a, b0, b1) \
    asm volatile("mma.sync.aligned.m16n8k16.row.col.f32.f16.f16.f32 " \
        "{%0,%1,%2,%3}, {%4,%5,%6,%7}, {%8,%9}, {%0,%1,%2,%3};" \
        : "+f"((d)[0]), "+f"((d)[1]), "+f"((d)[2]), "+f"((d)[3]) \
        : "r"((a)[0]), "r"((a)[1]), "r"((a)[2]), "r"((a)[3]), \
          "r"(b0), "r"(b1))

// fp16-accumulate HMMA (cross phases)
#define MMA16816F16(d, a, b0, b1) \
    asm volatile("mma.sync.aligned.m16n8k16.row.col.f16.f16.f16.f16 " \
        "{%0,%1}, {%2,%3,%4,%5}, {%6,%7}, {%0,%1};" \
        : "+r"((d)[0]), "+r"((d)[1]) \
        : "r"((a)[0]), "r"((a)[1]), "r"((a)[2]), "r"((a)[3]), \
          "r"(b0), "r"(b1))

// ---------------------------------------------------------------------------
// Deterministic mask partition per batch: Hillis-Steele inclusive scan.
// qidx[b][0..cnt) = selected positions (ascending), [cnt..1023] = complement.
// ---------------------------------------------------------------------------
__global__ void __launch_bounds__(1024) mask_scan_kernel(
    const int* __restrict__ qmask, const int* __restrict__ kmask,
    int* __restrict__ qidx, int* __restrict__ kidx,
    int* __restrict__ qcnt, int* __restrict__ kcnt)
{
    const int b = blockIdx.x;
    const int t = threadIdx.x;
    __shared__ int ps[1024];

#pragma unroll 1
    for (int pass = 0; pass < 2; pass++) {
        const int* mask = pass == 0 ? qmask : kmask;
        int*       idx  = pass == 0 ? qidx  : kidx;
        int*       cnt  = pass == 0 ? qcnt  : kcnt;
        const int m = mask[b * 1024 + t] != 0 ? 1 : 0;
        ps[t] = m;
        __syncthreads();
#pragma unroll
        for (int off = 1; off < 1024; off <<= 1) {
            int v = (t >= off) ? ps[t - off] : 0;
            __syncthreads();
            ps[t] += v;
            __syncthreads();
        }
        const int total = ps[1023];
        if (m) idx[b * 1024 + ps[t] - 1] = t;
        else   idx[b * 1024 + total + (t - ps[t])] = t;
        if (t == 0) cnt[b] = total;
        __syncthreads();
    }
}

// ---------------------------------------------------------------------------
// Split fp32 -> (hi, lo) fp16. grid.y selects among up to 2 tensors.
// ---------------------------------------------------------------------------
__global__ void __launch_bounds__(256) split_kernel(
    const float* __restrict__ x0, __half* __restrict__ h0o, __half* __restrict__ l0o,
    const float* __restrict__ x1, __half* __restrict__ h1o, __half* __restrict__ l1o,
    int n4)
{
    const float* x = (blockIdx.y == 0) ? x0 : x1;
    __half* h = (blockIdx.y == 0) ? h0o : h1o;
    __half* l = (blockIdx.y == 0) ? l0o : l1o;
    int i = blockIdx.x * 256 + threadIdx.x;
    if (i >= n4) return;
    float4 v = ((const float4*)x)[i];
    __half h0 = __float2half(v.x);
    __half h1 = __float2half(v.y);
    __half h2 = __float2half(v.z);
    __half h3 = __float2half(v.w);
    __half l0 = __float2half(v.x - __half2float(h0));
    __half l1 = __float2half(v.y - __half2float(h1));
    __half l2 = __float2half(v.z - __half2float(h2));
    __half l3 = __float2half(v.w - __half2float(h3));
    __half2* hp = (__half2*)(h + (size_t)i * 4);
    __half2* lp = (__half2*)(l + (size_t)i * 4);
    hp[0] = __halves2half2(h0, h1);
    hp[1] = __halves2half2(h2, h3);
    lp[0] = __halves2half2(l0, l1);
    lp[1] = __halves2half2(l2, l3);
}

// ---------------------------------------------------------------------------
// fp16x3 NT GEMM on mma.sync (round-10 champion core) + mask compaction:
//  - aCnt: per-batch live-row count; CTAs with m0 >= aCnt[bz] exit.
//  - aIdx: optional per-batch A-row gather (clamped to aCnt-1 for tile tails).
//  - bCnt: per-batch live-col count (EPI=0); CTAs with n0 >= bCnt[bz] exit.
// Garbage in tile tails beyond counts is written but never read downstream.
// 128x128x32 tile, 512 thr (16 warps 4x4, warp 32x32), 4-stage cp.async ring.
// Phase hh -> fp32 acc; hl+lh -> shared fp16 acc. 80B-padded smem rows.
// EPI=0: fp32 -> Cf. EPI=1: relu(acc+bias) re-split -> Ch/Cl fp16.
// ---------------------------------------------------------------------------
#define STG_BYTES 40960u           // 4 arrays * 128 rows * 80B
#define SMEM_BYTES (4u * STG_BYTES)

template <int EPI>
__global__ void __launch_bounds__(512, 1) gemm_fp16x3_kernel(
    const __half* __restrict__ Ah, const __half* __restrict__ Al,
    const __half* __restrict__ Bh, const __half* __restrict__ Bl,
    const float* __restrict__ bias,
    float* __restrict__ Cf,
    __half* __restrict__ Ch, __half* __restrict__ Cl,
    int K, long sAz, long sBz, long sCz, int N,
    const int* __restrict__ aIdx, const int* __restrict__ aCnt,
    const int* __restrict__ bCnt)
{
    extern __shared__ char smraw[];
    const uint32_t sb = smem_u32(smraw);
    const int tid = threadIdx.x;
    const int wid = tid >> 5;
    const int l   = tid & 31;

    const int bz = blockIdx.z;
    const long m0 = (long)blockIdx.y * 128;
    const long n0 = (long)blockIdx.x * 128;

    int mcnt = 1 << 30;
    if (aCnt) {
        mcnt = aCnt[bz];
        if (m0 >= mcnt) return;      // uniform CTA exit
    }
    if (bCnt && n0 >= bCnt[bz]) return;

    Ah += (long)bz * sAz;  Al += (long)bz * sAz;
    Bh += (long)bz * sBz;  Bl += (long)bz * sBz;
    if (EPI == 0) { Cf += (long)bz * sCz; }
    else          { Ch += (long)bz * sCz; Cl += (long)bz * sCz; }

    // --- cp.async coords: 512 threads -> (row 0..127, 16B chunk 0..3) ---
    const int lr = tid >> 2;
    const int lc = tid & 3;
    const uint32_t srow = (uint32_t)(lr * 80 + lc * 16);
    long arow = m0 + lr;
    if (aIdx) {
        long cl = arow < mcnt ? arow : (long)(mcnt - 1);
        arow = aIdx[(long)bz * 1024 + cl];
    }
    const __half* gAh = Ah + arow * (long)K + lc * 8;
    const __half* gAl = Al + arow * (long)K + lc * 8;
    const __half* gBh = Bh + (n0 + lr) * (long)K + lc * 8;
    const __half* gBl = Bl + (n0 + lr) * (long)K + lc * 8;

    // --- ldmatrix per-lane offsets (4x4 warp grid, warp tile 32x32) ---
    const int warpM = (wid >> 2) * 32;
    const int warpN = (wid & 3) * 32;
    const uint32_t aoff = (uint32_t)((warpM + (l & 15)) * 80 + (l >> 4) * 16);
    const uint32_t boff = (uint32_t)((warpN + (l & 7) + ((l >> 4) << 3)) * 80 +
                                     (((l >> 3) & 1) ? 16 : 0));

    auto load_stage = [&](int stage, int k0) {
        const uint32_t s = sb + (uint32_t)stage * STG_BYTES + srow;
        CP16(s,         gAh + k0);
        CP16(s + 10240, gAl + k0);
        CP16(s + 20480, gBh + k0);
        CP16(s + 30720, gBl + k0);
    };

    float acc[2][4][4];
    uint32_t accx[2][4][2];
#pragma unroll
    for (int i = 0; i < 2; i++)
#pragma unroll
        for (int j = 0; j < 4; j++) {
#pragma unroll
            for (int r = 0; r < 4; r++) acc[i][j][r] = 0.0f;
            accx[i][j][0] = 0u;
            accx[i][j][1] = 0u;
        }

    const int NK = K >> 5;   // K32 stages

    load_stage(0, 0);  CP_COMMIT();
    load_stage(1, 32); CP_COMMIT();
    load_stage(2, 64); CP_COMMIT();

    for (int t = 0; t < NK; t++) {
        CP_WAIT2();
        __syncthreads();

        const int tn3 = t + 3;
        if (tn3 < NK) load_stage(tn3 & 3, tn3 * 32);
        CP_COMMIT();

        const uint32_t sbase = sb + (uint32_t)(t & 3) * STG_BYTES;
#pragma unroll
        for (int ks = 0; ks < 2; ks++) {
            uint32_t ah[2][4], al[2][4], bh[2][4], bl[2][4];
#pragma unroll
            for (int mt = 0; mt < 2; mt++)
                LDSM4(ah[mt], sbase + aoff + mt * 1280 + ks * 32);
#pragma unroll
            for (int np = 0; np < 2; np++)
                LDSM4(bh[np], sbase + 20480 + boff + np * 1280 + ks * 32);
#pragma unroll
            for (int mt = 0; mt < 2; mt++)
#pragma unroll
                for (int nt = 0; nt < 4; nt++)
                    MMA16816(acc[mt][nt], ah[mt],
                             bh[nt >> 1][(nt & 1) * 2], bh[nt >> 1][(nt & 1) * 2 + 1]);
#pragma unroll
            for (int mt = 0; mt < 2; mt++)
                LDSM4(al[mt], sbase + 10240 + aoff + mt * 1280 + ks * 32);
#pragma unroll
            for (int np = 0; np < 2; np++)
                LDSM4(bl[np], sbase + 30720 + boff + np * 1280 + ks * 32);
#pragma unroll
            for (int mt = 0; mt < 2; mt++)
#pragma unroll
                for (int nt = 0; nt < 4; nt++)
                    MMA16816F16(accx[mt][nt], ah[mt],
                                bl[nt >> 1][(nt & 1) * 2], bl[nt >> 1][(nt & 1) * 2 + 1]);
#pragma unroll
            for (int mt = 0; mt < 2; mt++)
#pragma unroll
                for (int nt = 0; nt < 4; nt++)
                    MMA16816F16(accx[mt][nt], al[mt],
                                bh[nt >> 1][(nt & 1) * 2], bh[nt >> 1][(nt & 1) * 2 + 1]);
        }
    }

    // --- Epilogue: total = acc(fp32 hh) + accx(fp16 hl+lh) ---
    const int tm = l >> 2;
    const int tn = (l & 3) * 2;
#pragma unroll
    for (int mt = 0; mt < 2; mt++) {
        const long r0 = m0 + warpM + mt * 16 + tm;
        const long r1 = r0 + 8;
#pragma unroll
        for (int nt = 0; nt < 4; nt++) {
            const long col = n0 + warpN + nt * 8 + tn;
            float2 x01 = __half22float2(*(__half2*)&accx[mt][nt][0]);
            float2 x23 = __half22float2(*(__half2*)&accx[mt][nt][1]);
            float c0 = acc[mt][nt][0] + x01.x;
            float c1 = acc[mt][nt][1] + x01.y;
            float c2 = acc[mt][nt][2] + x23.x;
            float c3 = acc[mt][nt][3] + x23.y;
            if (EPI == 0) {
                *(float2*)(Cf + r0 * (long)N + col) = make_float2(c0, c1);
                *(float2*)(Cf + r1 * (long)N + col) = make_float2(c2, c3);
            } else {
                const float b0 = bias[col], b1 = bias[col + 1];
                float v0 = fmaxf(c0 + b0, 0.0f);
                float v1 = fmaxf(c1 + b1, 0.0f);
                float v2 = fmaxf(c2 + b0, 0.0f);
                float v3 = fmaxf(c3 + b1, 0.0f);
                __half h0 = __float2half(v0), h1 = __float2half(v1);
                __half h2 = __float2half(v2), h3 = __float2half(v3);
                __half e0 = __float2half(v0 - __half2float(h0));
                __half e1 = __float2half(v1 - __half2float(h1));
                __half e2 = __float2half(v2 - __half2float(h2));
                __half e3 = __float2half(v3 - __half2float(h3));
                *(__half2*)(Ch + r0 * (long)N + col) = __halves2half2(h0, h1);
                *(__half2*)(Ch + r1 * (long)N + col) = __halves2half2(h2, h3);
                *(__half2*)(Cl + r0 * (long)N + col) = __halves2half2(e0, e1);
                *(__half2*)(Cl + r1 * (long)N + col) = __halves2half2(e2, e3);
            }
        }
    }
}

// ---------------------------------------------------------------------------
// Softmax over compacted logits + scatter to full output.
// Block (i, b): if i < qcnt: softmax over kcnt compacted cols, scatter into a
// zeroed smem row via kidx, write full row to out[b][qidx[i]].
// Else: write zero row to out[b][qidx[i]] (complement positions).
// Exactness: dropped keys contribute exp(-1e9 - max) == 0.0f in the reference.
// ---------------------------------------------------------------------------
__global__ void __launch_bounds__(256) softmax_scatter_kernel(
    const float* __restrict__ logc,
    const int* __restrict__ qidx, const int* __restrict__ kidx,
    const int* __restrict__ qcnt, const int* __restrict__ kcnt,
    float* __restrict__ out)
{
    const int b = blockIdx.y;
    const int i = blockIdx.x;
    const int tid = threadIdx.x;
    const int qc = qcnt[b];
    const int orow = qidx[b * 1024 + i];
    float* dst = out + ((long)b * 1024 + orow) * 1024;

    if (i >= qc) {
        ((float4*)dst)[tid] = make_float4(0.f, 0.f, 0.f, 0.f);
        return;
    }

    const int kc = kcnt[b];
    const float* src = logc + ((long)b * 1024 + i) * 1024;
    const int j0 = tid * 4;

    __shared__ float row[1024];
    __shared__ float red[8];

    float4 v = ((const float4*)src)[tid];
    float x0 = (j0 + 0 < kc) ? v.x : -1e30f;
    float x1 = (j0 + 1 < kc) ? v.y : -1e30f;
    float x2 = (j0 + 2 < kc) ? v.z : -1e30f;
    float x3 = (j0 + 3 < kc) ? v.w : -1e30f;

    float mx = fmaxf(fmaxf(x0, x1), fmaxf(x2, x3));
#pragma unroll
    for (int o = 16; o > 0; o >>= 1)
        mx = fmaxf(mx, __shfl_xor_sync(0xFFFFFFFFu, mx, o));
    if ((tid & 31) == 0) red[tid >> 5] = mx;
    __syncthreads();
    float bmx = red[0];
#pragma unroll
    for (int w = 1; w < 8; w++) bmx = fmaxf(bmx, red[w]);
    __syncthreads();

    float e0 = expf(x0 - bmx);
    float e1 = expf(x1 - bmx);
    float e2 = expf(x2 - bmx);
    float e3 = expf(x3 - bmx);
    float s = e0 + e1 + e2 + e3;
#pragma unroll
    for (int o = 16; o > 0; o >>= 1)
        s += __shfl_xor_sync(0xFFFFFFFFu, s, o);
    if ((tid & 31) == 0) red[tid >> 5] = s;
    __syncthreads();
    float bs = 0.0f;
#pragma unroll
    for (int w = 0; w < 8; w++) bs += red[w];
    const float inv = 1.0f / bs;

    // zero smem row, then scatter
    ((float4*)row)[tid] = make_float4(0.f, 0.f, 0.f, 0.f);
    __syncthreads();
    const int* kix = kidx + b * 1024;
    if (j0 + 0 < kc) row[kix[j0 + 0]] = e0 * inv;
    if (j0 + 1 < kc) row[kix[j0 + 1]] = e1 * inv;
    if (j0 + 2 < kc) row[kix[j0 + 2]] = e2 * inv;
    if (j0 + 3 < kc) row[kix[j0 + 3]] = e3 * inv;
    __syncthreads();

    ((float4*)dst)[tid] = ((float4*)row)[tid];
}

// ---------------------------------------------------------------------------
// kernel_launch
// Inputs: query, key, query_mask, key_mask, Wq, bq, Wk, bk
// ---------------------------------------------------------------------------
extern "C" void kernel_launch(void* const* d_in, const int* in_sizes, int n_in,
                              void* d_out, int out_size)
{
    const float* query = (const float*)d_in[0];
    const float* key   = (const float*)d_in[1];
    const int*   qmask = (const int*)  d_in[2];
    const int*   kmask = (const int*)  d_in[3];
    const float* Wq    = (const float*)d_in[4];
    const float* bq    = (const float*)d_in[5];
    const float* Wk    = (const float*)d_in[6];
    const float* bk    = (const float*)d_in[7];
    float* out = (float*)d_out;

    __half *qh, *ql, *kh, *kl, *wqh, *wql, *wkh, *wkl;
    __half *qph, *qpl, *kph, *kpl;
    float* logc;
    int *qidx, *kidx, *qcnt, *kcnt;
    cudaGetSymbolAddress((void**)&qh,   g_qh);
    cudaGetSymbolAddress((void**)&ql,   g_ql);
    cudaGetSymbolAddress((void**)&kh,   g_kh);
    cudaGetSymbolAddress((void**)&kl,   g_kl);
    cudaGetSymbolAddress((void**)&wqh,  g_wqh);
    cudaGetSymbolAddress((void**)&wql,  g_wql);
    cudaGetSymbolAddress((void**)&wkh,  g_wkh);
    cudaGetSymbolAddress((void**)&wkl,  g_wkl);
    cudaGetSymbolAddress((void**)&qph,  g_qph);
    cudaGetSymbolAddress((void**)&qpl,  g_qpl);
    cudaGetSymbolAddress((void**)&kph,  g_kph);
    cudaGetSymbolAddress((void**)&kpl,  g_kpl);
    cudaGetSymbolAddress((void**)&logc, g_logc);
    cudaGetSymbolAddress((void**)&qidx, g_qidx);
    cudaGetSymbolAddress((void**)&kidx, g_kidx);
    cudaGetSymbolAddress((void**)&qcnt, g_qcnt);
    cudaGetSymbolAddress((void**)&kcnt, g_kcnt);

    cudaFuncSetAttribute(gemm_fp16x3_kernel<0>,
                         cudaFuncAttributeMaxDynamicSharedMemorySize, SMEM_BYTES);
    cudaFuncSetAttribute(gemm_fp16x3_kernel<1>,
                         cudaFuncAttributeMaxDynamicSharedMemorySize, SMEM_BYTES);

    // Deterministic mask partition (selected positions, then complement)
    mask_scan_kernel<<<BATCH, 1024>>>(qmask, kmask, qidx, kidx, qcnt, kcnt);

    // Split fp32 inputs into fp16 hi/lo
    dim3 gs_big((unsigned)((QN / 4) / 256), 2);   // 32768 x 2
    split_kernel<<<gs_big, 256>>>(query, qh, ql, key, kh, kl, (int)(QN / 4));
    dim3 gs_w((unsigned)((WN / 4) / 256), 2);     // 1024 x 2
    split_kernel<<<gs_w, 256>>>(Wq, wqh, wql, Wk, wkh, wkl, (int)(WN / 4));

    // Projections on SELECTED rows only (gather via qidx/kidx), batched.
    // Output rows are compacted per batch.
    dim3 gproj(HID / 128, LQ / 128, BATCH);   // (8, 8, 32); ~44% CTAs exit early
    gemm_fp16x3_kernel<1><<<gproj, 512, SMEM_BYTES>>>(
        qh, ql, wqh, wql, bq, nullptr, qph, qpl,
        KDIM, (long)LQ * KDIM, 0, (long)LQ * HID, HID,
        qidx, qcnt, nullptr);
    gemm_fp16x3_kernel<1><<<gproj, 512, SMEM_BYTES>>>(
        kh, kl, wkh, wkl, bk, nullptr, kph, kpl,
        KDIM, (long)LK * KDIM, 0, (long)LK * HID, HID,
        kidx, kcnt, nullptr);

    // Compacted batched logits: rows < qcnt[b], cols < kcnt[b] (~32% of work)
    dim3 glog(LK / 128, LQ / 128, BATCH);
    gemm_fp16x3_kernel<0><<<glog, 512, SMEM_BYTES>>>(
        qph, qpl, kph, kpl, nullptr, logc, nullptr, nullptr,
        HID, (long)LQ * HID, (long)LK * HID, (long)LQ * LK, LK,
        nullptr, qcnt, kcnt);

    // Softmax over compacted cols + scatter to full output (zeros elsewhere)
    dim3 gsm(LQ, BATCH);
    softmax_scatter_kernel<<<gsm, 256>>>(logc, qidx, kidx, qcnt, kcnt, out);
}

// round 14
// speedup vs baseline: 2.1257x; 1.1204x over previous
#include <cuda_runtime.h>
#include <cuda_fp16.h>
#include <cstdint>
#include <math.h>

#define BATCH 32
#define LQ    1024
#define LK    1024
#define HID   1024
#define KDIM  1024

// ---------------------------------------------------------------------------
// Device scratch (BSS, no runtime allocation). +128 pad rows where GEMM tile
// tails can read past the live region (all-selected corner case).
// ---------------------------------------------------------------------------
#define QN   ((size_t)BATCH * LQ * KDIM)         // 33,554,432
#define QNP  (QN + (size_t)128 * KDIM)           // +128 pad rows
#define WN   ((size_t)HID * KDIM)
__device__ __half g_qh[QNP],  g_ql[QNP];          // compacted split inputs
__device__ __half g_kh[QNP],  g_kl[QNP];
__device__ __half g_wqh[WN],  g_wql[WN];
__device__ __half g_wkh[WN],  g_wkl[WN];
__device__ __half g_qph[QNP], g_qpl[QNP];         // compacted projected q
__device__ __half g_kph[QNP], g_kpl[QNP];         // compacted projected k
__device__ float  g_logc[QN];                     // per-batch compacted logits
__device__ int    g_qidx[BATCH * LQ];
__device__ int    g_kidx[BATCH * LK];
__device__ int    g_qcnt[BATCH];
__device__ int    g_kcnt[BATCH];
__device__ int    g_qoff[BATCH + 1];              // exclusive scan; [32] = total
__device__ int    g_koff[BATCH + 1];

// ---------------------------------------------------------------------------
// PTX helpers (portable compute_103 ISA: cp.async / ldmatrix / mma.sync)
// ---------------------------------------------------------------------------
__device__ __forceinline__ uint32_t smem_u32(const void* p) {
    uint32_t a;
    asm("{ .reg .u64 t; cvta.to.shared.u64 t, %1; cvt.u32.u64 %0, t; }"
        : "=r"(a) : "l"(p));
    return a;
}

#define CP16(smem, gmem) \
    asm volatile("cp.async.cg.shared.global [%0], [%1], 16;" \
                 :: "r"(smem), "l"(gmem))
#define CP_COMMIT() asm volatile("cp.async.commit_group;" ::: "memory")
#define CP_WAIT2()  asm volatile("cp.async.wait_group 2;" ::: "memory")

#define LDSM4(r, addr) \
    asm volatile("ldmatrix.sync.aligned.m8n8.x4.shared.b16 {%0,%1,%2,%3}, [%4];" \
        : "=r"((r)[0]), "=r"((r)[1]), "=r"((r)[2]), "=r"((r)[3]) : "r"(addr))

#define MMA16816(d, a, b0, b1) \
    asm volatile("mma.sync.aligned.m16n8k16.row.col.f32.f16.f16.f32 " \
        "{%0,%1,%2,%3}, {%4,%5,%6,%7}, {%8,%9}, {%0,%1,%2,%3};" \
        : "+f"((d)[0]), "+f"((d)[1]), "+f"((d)[2]), "+f"((d)[3]) \
        : "r"((a)[0]), "r"((a)[1]), "r"((a)[2]), "r"((a)[3]), \
          "r"(b0), "r"(b1))

#define MMA16816F16(d, a, b0, b1) \
    asm volatile("mma.sync.aligned.m16n8k16.row.col.f16.f16.f16.f16 " \
        "{%0,%1}, {%2,%3,%4,%5}, {%6,%7}, {%0,%1};" \
        : "+r"((d)[0]), "+r"((d)[1]) \
        : "r"((a)[0]), "r"((a)[1]), "r"((a)[2]), "r"((a)[3]), \
          "r"(b0), "r"(b1))

// ---------------------------------------------------------------------------
// Deterministic mask partition per batch (Hillis-Steele scan).
// ---------------------------------------------------------------------------
__global__ void __launch_bounds__(1024) mask_scan_kernel(
    const int* __restrict__ qmask, const int* __restrict__ kmask,
    int* __restrict__ qidx, int* __restrict__ kidx,
    int* __restrict__ qcnt, int* __restrict__ kcnt)
{
    const int b = blockIdx.x;
    const int t = threadIdx.x;
    __shared__ int ps[1024];

#pragma unroll 1
    for (int pass = 0; pass < 2; pass++) {
        const int* mask = pass == 0 ? qmask : kmask;
        int*       idx  = pass == 0 ? qidx  : kidx;
        int*       cnt  = pass == 0 ? qcnt  : kcnt;
        const int m = mask[b * 1024 + t] != 0 ? 1 : 0;
        ps[t] = m;
        __syncthreads();
#pragma unroll
        for (int off = 1; off < 1024; off <<= 1) {
            int v = (t >= off) ? ps[t - off] : 0;
            __syncthreads();
            ps[t] += v;
            __syncthreads();
        }
        const int total = ps[1023];
        if (m) idx[b * 1024 + ps[t] - 1] = t;
        else   idx[b * 1024 + total + (t - ps[t])] = t;
        if (t == 0) cnt[b] = total;
        __syncthreads();
    }
}

// Exclusive scan of per-batch counts (32 elements; serial, trivial).
__global__ void offsets_kernel(const int* __restrict__ qcnt,
                               const int* __restrict__ kcnt,
                               int* __restrict__ qoff, int* __restrict__ koff)
{
    if (threadIdx.x == 0) {
        int s = 0;
        for (int b = 0; b < BATCH; b++) { qoff[b] = s; s += qcnt[b]; }
        qoff[BATCH] = s;
    }
    if (threadIdx.x == 1) {
        int s = 0;
        for (int b = 0; b < BATCH; b++) { koff[b] = s; s += kcnt[b]; }
        koff[BATCH] = s;
    }
}

// ---------------------------------------------------------------------------
// Gather-split: convert ONLY selected rows fp32 -> (hi,lo) fp16, writing them
// globally compacted (row off[b]+i). Block = one row; 256 thr x float4.
// ---------------------------------------------------------------------------
__global__ void __launch_bounds__(256) split_gather_kernel(
    const float* __restrict__ x, const int* __restrict__ idx,
    const int* __restrict__ cnt, const int* __restrict__ off,
    __half* __restrict__ h, __half* __restrict__ l)
{
    const int b = blockIdx.y;
    const int i = blockIdx.x;
    if (i >= cnt[b]) return;
    const int t = threadIdx.x;
    const int src = idx[b * 1024 + i];
    const float* srow = x + ((long)b * 1024 + src) * 1024;
    const long drow = (long)(off[b] + i) * 1024;

    float4 v = ((const float4*)srow)[t];
    __half h0 = __float2half(v.x);
    __half h1 = __float2half(v.y);
    __half h2 = __float2half(v.z);
    __half h3 = __float2half(v.w);
    __half l0 = __float2half(v.x - __half2float(h0));
    __half l1 = __float2half(v.y - __half2float(h1));
    __half l2 = __float2half(v.z - __half2float(h2));
    __half l3 = __float2half(v.w - __half2float(h3));
    __half2* hp = (__half2*)(h + drow + (size_t)t * 4);
    __half2* lp = (__half2*)(l + drow + (size_t)t * 4);
    hp[0] = __halves2half2(h0, h1);
    hp[1] = __halves2half2(h2, h3);
    lp[0] = __halves2half2(l0, l1);
    lp[1] = __halves2half2(l2, l3);
}

// Plain split for the weights (full tensors, small).
__global__ void __launch_bounds__(256) split_kernel(
    const float* __restrict__ x0, __half* __restrict__ h0o, __half* __restrict__ l0o,
    const float* __restrict__ x1, __half* __restrict__ h1o, __half* __restrict__ l1o,
    int n4)
{
    const float* x = (blockIdx.y == 0) ? x0 : x1;
    __half* h = (blockIdx.y == 0) ? h0o : h1o;
    __half* l = (blockIdx.y == 0) ? l0o : l1o;
    int i = blockIdx.x * 256 + threadIdx.x;
    if (i >= n4) return;
    float4 v = ((const float4*)x)[i];
    __half h0 = __float2half(v.x);
    __half h1 = __float2half(v.y);
    __half h2 = __float2half(v.z);
    __half h3 = __float2half(v.w);
    __half l0 = __float2half(v.x - __half2float(h0));
    __half l1 = __float2half(v.y - __half2float(h1));
    __half l2 = __float2half(v.z - __half2float(h2));
    __half l3 = __float2half(v.w - __half2float(h3));
    __half2* hp = (__half2*)(h + (size_t)i * 4);
    __half2* lp = (__half2*)(l + (size_t)i * 4);
    hp[0] = __halves2half2(h0, h1);
    hp[1] = __halves2half2(h2, h3);
    lp[0] = __halves2half2(l0, l1);
    lp[1] = __halves2half2(l2, l3);
}

// ---------------------------------------------------------------------------
// fp16x3 NT GEMM (round-13 core) with offset-based batching:
//  row base A = aOff[bz] (0 if null), live rows aCnt[bz]; same for B.
//  CTAs beyond counts exit. Tile-tail rows read valid-but-foreign or zero rows
//  (bounds audited; outputs in those cells are never read downstream).
// EPI=0: fp32 -> Cf + bz*sCz (per-batch layout). EPI=1: relu(acc+bias),
// re-split hi/lo -> Ch/Cl at global row m0+... (compacted).
// ---------------------------------------------------------------------------
#define STG_BYTES 40960u
#define SMEM_BYTES (4u * STG_BYTES)

template <int EPI>
__global__ void __launch_bounds__(512, 1) gemm_fp16x3_kernel(
    const __half* __restrict__ Ah, const __half* __restrict__ Al,
    const __half* __restrict__ Bh, const __half* __restrict__ Bl,
    const float* __restrict__ bias,
    float* __restrict__ Cf,
    __half* __restrict__ Ch, __half* __restrict__ Cl,
    int K, int N, long sCz,
    const int* __restrict__ aOff, const int* __restrict__ aCnt,
    const int* __restrict__ bOff, const int* __restrict__ bCnt)
{
    extern __shared__ char smraw[];
    const uint32_t sb = smem_u32(smraw);
    const int tid = threadIdx.x;
    const int wid = tid >> 5;
    const int l   = tid & 31;

    const int bz = blockIdx.z;
    const long m0 = (long)blockIdx.y * 128;
    const long n0 = (long)blockIdx.x * 128;

    if (aCnt && m0 >= aCnt[bz]) return;
    if (bCnt && n0 >= bCnt[bz]) return;
    const long abase = aOff ? aOff[bz] : 0;
    const long bbase = bOff ? bOff[bz] : 0;
    if (EPI == 0) Cf += (long)bz * sCz;

    // --- cp.async coords ---
    const int lr = tid >> 2;
    const int lc = tid & 3;
    const uint32_t srow = (uint32_t)(lr * 80 + lc * 16);
    const __half* gAh = Ah + (abase + m0 + lr) * (long)K + lc * 8;
    const __half* gAl = Al + (abase + m0 + lr) * (long)K + lc * 8;
    const __half* gBh = Bh + (bbase + n0 + lr) * (long)K + lc * 8;
    const __half* gBl = Bl + (bbase + n0 + lr) * (long)K + lc * 8;

    // --- ldmatrix per-lane offsets (4x4 warp grid, warp tile 32x32) ---
    const int warpM = (wid >> 2) * 32;
    const int warpN = (wid & 3) * 32;
    const uint32_t aoff = (uint32_t)((warpM + (l & 15)) * 80 + (l >> 4) * 16);
    const uint32_t boff = (uint32_t)((warpN + (l & 7) + ((l >> 4) << 3)) * 80 +
                                     (((l >> 3) & 1) ? 16 : 0));

    auto load_stage = [&](int stage, int k0) {
        const uint32_t s = sb + (uint32_t)stage * STG_BYTES + srow;
        CP16(s,         gAh + k0);
        CP16(s + 10240, gAl + k0);
        CP16(s + 20480, gBh + k0);
        CP16(s + 30720, gBl + k0);
    };

    float acc[2][4][4];
    uint32_t accx[2][4][2];
#pragma unroll
    for (int i = 0; i < 2; i++)
#pragma unroll
        for (int j = 0; j < 4; j++) {
#pragma unroll
            for (int r = 0; r < 4; r++) acc[i][j][r] = 0.0f;
            accx[i][j][0] = 0u;
            accx[i][j][1] = 0u;
        }

    const int NK = K >> 5;

    load_stage(0, 0);  CP_COMMIT();
    load_stage(1, 32); CP_COMMIT();
    load_stage(2, 64); CP_COMMIT();

    for (int t = 0; t < NK; t++) {
        CP_WAIT2();
        __syncthreads();

        const int tn3 = t + 3;
        if (tn3 < NK) load_stage(tn3 & 3, tn3 * 32);
        CP_COMMIT();

        const uint32_t sbase = sb + (uint32_t)(t & 3) * STG_BYTES;
#pragma unroll
        for (int ks = 0; ks < 2; ks++) {
            uint32_t ah[2][4], al[2][4], bh[2][4], bl[2][4];
#pragma unroll
            for (int mt = 0; mt < 2; mt++)
                LDSM4(ah[mt], sbase + aoff + mt * 1280 + ks * 32);
#pragma unroll
            for (int np = 0; np < 2; np++)
                LDSM4(bh[np], sbase + 20480 + boff + np * 1280 + ks * 32);
#pragma unroll
            for (int mt = 0; mt < 2; mt++)
#pragma unroll
                for (int nt = 0; nt < 4; nt++)
                    MMA16816(acc[mt][nt], ah[mt],
                             bh[nt >> 1][(nt & 1) * 2], bh[nt >> 1][(nt & 1) * 2 + 1]);
#pragma unroll
            for (int mt = 0; mt < 2; mt++)
                LDSM4(al[mt], sbase + 10240 + aoff + mt * 1280 + ks * 32);
#pragma unroll
            for (int np = 0; np < 2; np++)
                LDSM4(bl[np], sbase + 30720 + boff + np * 1280 + ks * 32);
#pragma unroll
            for (int mt = 0; mt < 2; mt++)
#pragma unroll
                for (int nt = 0; nt < 4; nt++)
                    MMA16816F16(accx[mt][nt], ah[mt],
                                bl[nt >> 1][(nt & 1) * 2], bl[nt >> 1][(nt & 1) * 2 + 1]);
#pragma unroll
            for (int mt = 0; mt < 2; mt++)
#pragma unroll
                for (int nt = 0; nt < 4; nt++)
                    MMA16816F16(accx[mt][nt], al[mt],
                                bh[nt >> 1][(nt & 1) * 2], bh[nt >> 1][(nt & 1) * 2 + 1]);
        }
    }

    const int tm = l >> 2;
    const int tn = (l & 3) * 2;
#pragma unroll
    for (int mt = 0; mt < 2; mt++) {
        const long r0 = m0 + warpM + mt * 16 + tm;
        const long r1 = r0 + 8;
#pragma unroll
        for (int nt = 0; nt < 4; nt++) {
            const long col = n0 + warpN + nt * 8 + tn;
            float2 x01 = __half22float2(*(__half2*)&accx[mt][nt][0]);
            float2 x23 = __half22float2(*(__half2*)&accx[mt][nt][1]);
            float c0 = acc[mt][nt][0] + x01.x;
            float c1 = acc[mt][nt][1] + x01.y;
            float c2 = acc[mt][nt][2] + x23.x;
            float c3 = acc[mt][nt][3] + x23.y;
            if (EPI == 0) {
                *(float2*)(Cf + r0 * (long)N + col) = make_float2(c0, c1);
                *(float2*)(Cf + r1 * (long)N + col) = make_float2(c2, c3);
            } else {
                const float b0 = bias[col], b1 = bias[col + 1];
                float v0 = fmaxf(c0 + b0, 0.0f);
                float v1 = fmaxf(c1 + b1, 0.0f);
                float v2 = fmaxf(c2 + b0, 0.0f);
                float v3 = fmaxf(c3 + b1, 0.0f);
                __half h0 = __float2half(v0), h1 = __float2half(v1);
                __half h2 = __float2half(v2), h3 = __float2half(v3);
                __half e0 = __float2half(v0 - __half2float(h0));
                __half e1 = __float2half(v1 - __half2float(h1));
                __half e2 = __float2half(v2 - __half2float(h2));
                __half e3 = __float2half(v3 - __half2float(h3));
                *(__half2*)(Ch + r0 * (long)N + col) = __halves2half2(h0, h1);
                *(__half2*)(Ch + r1 * (long)N + col) = __halves2half2(h2, h3);
                *(__half2*)(Cl + r0 * (long)N + col) = __halves2half2(e0, e1);
                *(__half2*)(Cl + r1 * (long)N + col) = __halves2half2(e2, e3);
            }
        }
    }
}

// ---------------------------------------------------------------------------
// Softmax over compacted cols + scatter to full output (exact vs reference).
// ---------------------------------------------------------------------------
__global__ void __launch_bounds__(256) softmax_scatter_kernel(
    const float* __restrict__ logc,
    const int* __restrict__ qidx, const int* __restrict__ kidx,
    const int* __restrict__ qcnt, const int* __restrict__ kcnt,
    float* __restrict__ out)
{
    const int b = blockIdx.y;
    const int i = blockIdx.x;
    const int tid = threadIdx.x;
    const int qc = qcnt[b];
    const int orow = qidx[b * 1024 + i];
    float* dst = out + ((long)b * 1024 + orow) * 1024;

    if (i >= qc) {
        ((float4*)dst)[tid] = make_float4(0.f, 0.f, 0.f, 0.f);
        return;
    }

    const int kc = kcnt[b];
    const float* src = logc + ((long)b * 1024 + i) * 1024;
    const int j0 = tid * 4;

    __shared__ float row[1024];
    __shared__ float red[8];

    float4 v = ((const float4*)src)[tid];
    float x0 = (j0 + 0 < kc) ? v.x : -1e30f;
    float x1 = (j0 + 1 < kc) ? v.y : -1e30f;
    float x2 = (j0 + 2 < kc) ? v.z : -1e30f;
    float x3 = (j0 + 3 < kc) ? v.w : -1e30f;

    float mx = fmaxf(fmaxf(x0, x1), fmaxf(x2, x3));
#pragma unroll
    for (int o = 16; o > 0; o >>= 1)
        mx = fmaxf(mx, __shfl_xor_sync(0xFFFFFFFFu, mx, o));
    if ((tid & 31) == 0) red[tid >> 5] = mx;
    __syncthreads();
    float bmx = red[0];
#pragma unroll
    for (int w = 1; w < 8; w++) bmx = fmaxf(bmx, red[w]);
    __syncthreads();

    float e0 = expf(x0 - bmx);
    float e1 = expf(x1 - bmx);
    float e2 = expf(x2 - bmx);
    float e3 = expf(x3 - bmx);
    float s = e0 + e1 + e2 + e3;
#pragma unroll
    for (int o = 16; o > 0; o >>= 1)
        s += __shfl_xor_sync(0xFFFFFFFFu, s, o);
    if ((tid & 31) == 0) red[tid >> 5] = s;
    __syncthreads();
    float bs = 0.0f;
#pragma unroll
    for (int w = 0; w < 8; w++) bs += red[w];
    const float inv = 1.0f / bs;

    ((float4*)row)[tid] = make_float4(0.f, 0.f, 0.f, 0.f);
    __syncthreads();
    const int* kix = kidx + b * 1024;
    if (j0 + 0 < kc) row[kix[j0 + 0]] = e0 * inv;
    if (j0 + 1 < kc) row[kix[j0 + 1]] = e1 * inv;
    if (j0 + 2 < kc) row[kix[j0 + 2]] = e2 * inv;
    if (j0 + 3 < kc) row[kix[j0 + 3]] = e3 * inv;
    __syncthreads();

    ((float4*)dst)[tid] = ((float4*)row)[tid];
}

// ---------------------------------------------------------------------------
// kernel_launch
// Inputs: query, key, query_mask, key_mask, Wq, bq, Wk, bk
// ---------------------------------------------------------------------------
extern "C" void kernel_launch(void* const* d_in, const int* in_sizes, int n_in,
                              void* d_out, int out_size)
{
    const float* query = (const float*)d_in[0];
    const float* key   = (const float*)d_in[1];
    const int*   qmask = (const int*)  d_in[2];
    const int*   kmask = (const int*)  d_in[3];
    const float* Wq    = (const float*)d_in[4];
    const float* bq    = (const float*)d_in[5];
    const float* Wk    = (const float*)d_in[6];
    const float* bk    = (const float*)d_in[7];
    float* out = (float*)d_out;

    __half *qh, *ql, *kh, *kl, *wqh, *wql, *wkh, *wkl;
    __half *qph, *qpl, *kph, *kpl;
    float* logc;
    int *qidx, *kidx, *qcnt, *kcnt, *qoff, *koff;
    cudaGetSymbolAddress((void**)&qh,   g_qh);
    cudaGetSymbolAddress((void**)&ql,   g_ql);
    cudaGetSymbolAddress((void**)&kh,   g_kh);
    cudaGetSymbolAddress((void**)&kl,   g_kl);
    cudaGetSymbolAddress((void**)&wqh,  g_wqh);
    cudaGetSymbolAddress((void**)&wql,  g_wql);
    cudaGetSymbolAddress((void**)&wkh,  g_wkh);
    cudaGetSymbolAddress((void**)&wkl,  g_wkl);
    cudaGetSymbolAddress((void**)&qph,  g_qph);
    cudaGetSymbolAddress((void**)&qpl,  g_qpl);
    cudaGetSymbolAddress((void**)&kph,  g_kph);
    cudaGetSymbolAddress((void**)&kpl,  g_kpl);
    cudaGetSymbolAddress((void**)&logc, g_logc);
    cudaGetSymbolAddress((void**)&qidx, g_qidx);
    cudaGetSymbolAddress((void**)&kidx, g_kidx);
    cudaGetSymbolAddress((void**)&qcnt, g_qcnt);
    cudaGetSymbolAddress((void**)&kcnt, g_kcnt);
    cudaGetSymbolAddress((void**)&qoff, g_qoff);
    cudaGetSymbolAddress((void**)&koff, g_koff);

    cudaFuncSetAttribute(gemm_fp16x3_kernel<0>,
                         cudaFuncAttributeMaxDynamicSharedMemorySize, SMEM_BYTES);
    cudaFuncSetAttribute(gemm_fp16x3_kernel<1>,
                         cudaFuncAttributeMaxDynamicSharedMemorySize, SMEM_BYTES);

    // Mask partition + global offsets
    mask_scan_kernel<<<BATCH, 1024>>>(qmask, kmask, qidx, kidx, qcnt, kcnt);
    offsets_kernel<<<1, 32>>>(qcnt, kcnt, qoff, koff);

    // Gather-split: selected rows only, globally compacted
    dim3 gsg(LQ, BATCH);
    split_gather_kernel<<<gsg, 256>>>(query, qidx, qcnt, qoff, qh, ql);
    split_gather_kernel<<<gsg, 256>>>(key,   kidx, kcnt, koff, kh, kl);
    // Weights (full split, small)
    dim3 gs_w((unsigned)((WN / 4) / 256), 2);
    split_kernel<<<gs_w, 256>>>(Wq, wqh, wql, Wk, wkh, wkl, (int)(WN / 4));

    // Projections over globally-compacted rows (dynamic M, early-exit tiles)
    dim3 gproj(HID / 128, (BATCH * LQ) / 128, 1);   // (8, 256, 1)
    gemm_fp16x3_kernel<1><<<gproj, 512, SMEM_BYTES>>>(
        qh, ql, wqh, wql, bq, nullptr, qph, qpl,
        KDIM, HID, 0, nullptr, qoff + BATCH, nullptr, nullptr);
    gemm_fp16x3_kernel<1><<<gproj, 512, SMEM_BYTES>>>(
        kh, kl, wkh, wkl, bk, nullptr, kph, kpl,
        KDIM, HID, 0, nullptr, koff + BATCH, nullptr, nullptr);

    // Batched compacted logits: rows qoff[b]+[0,qcnt), cols koff[b]+[0,kcnt)
    dim3 glog(LK / 128, LQ / 128, BATCH);
    gemm_fp16x3_kernel<0><<<glog, 512, SMEM_BYTES>>>(
        qph, qpl, kph, kpl, nullptr, logc, nullptr, nullptr,
        HID, LK, (long)LQ * LK, qoff, qcnt, koff, kcnt);

    // Softmax over compacted cols + scatter to full output
    dim3 gsm(LQ, BATCH);
    softmax_scatter_kernel<<<gsm, 256>>>(logc, qidx, kidx, qcnt, kcnt, out);
}